// round 14
// baseline (speedup 1.0000x reference)
#include <cuda_runtime.h>
#include <cuda_fp16.h>
#include <cstdint>

#define B2   8192
#define D    512
#define KD   2048      // fp16 cols: [0,1024) hi, [1024,2048) lo
#define NM1  8191

#define TM   256
#define TNM  96        // tensor columns per tile
#define TNF  32        // fma columns per tile
#define BK   64
#define NSTG 3
#define NCH  48        // 32 cross (fp16 acc) + 16 hihi (fp32 acc)

#define ROWB 144
#define A_SZ (256 * ROWB)              // 36864
#define B_SZ (96 * ROWB)               // 13824
#define STAGE_SZ (A_SZ + B_SZ)         // 50688
#define BBASE (NSTG * STAGE_SZ)        // 152064
#define BBLK  32768                    // fp32 b-block (bx 16K + by 16K)
#define SM_TOTAL (BBASE + 2 * BBLK)    // 217600

// ---------------- device scratch ----------------
__device__ __align__(128) __half g_Ah[(size_t)B2 * KD];
__device__ __align__(128) __half g_Bh[(size_t)B2 * KD];
__device__ __align__(128) float2 g_A32[(size_t)D * B2];   // (x^2, x)  d-major
__device__ __align__(128) float  g_B1[(size_t)D * B2];    // 1/s       d-major
__device__ __align__(128) float  g_B2[(size_t)D * B2];    // -2x/s     d-major
__device__ float g_t3[B2];
__device__ float g_ls[B2];
__device__ float g_c[B2];
__device__ float g_cj[B2];
__device__ float g_rowsum[B2];

// ---------------- PTX helpers ----------------
__device__ __forceinline__ uint32_t smem_u32(const void* p) {
    uint32_t a;
    asm("{ .reg .u64 t; cvta.to.shared.u64 t, %1; cvt.u32.u64 %0, t; }" : "=r"(a) : "l"(p));
    return a;
}
__device__ __forceinline__ void cp_async16(uint32_t dst, const void* src) {
    asm volatile("cp.async.cg.shared.global [%0], [%1], 16;" :: "r"(dst), "l"(src) : "memory");
}
__device__ __forceinline__ void cp_async8(uint32_t dst, const void* src) {
    asm volatile("cp.async.ca.shared.global [%0], [%1], 8;" :: "r"(dst), "l"(src) : "memory");
}
__device__ __forceinline__ void cp_commit() {
    asm volatile("cp.async.commit_group;" ::: "memory");
}
template <int N> __device__ __forceinline__ void cp_wait() {
    asm volatile("cp.async.wait_group %0;" :: "n"(N) : "memory");
}
__device__ __forceinline__ void ldsm4(uint32_t addr, uint32_t* r) {
    asm volatile("ldmatrix.sync.aligned.m8n8.x4.shared.b16 {%0,%1,%2,%3}, [%4];"
                 : "=r"(r[0]), "=r"(r[1]), "=r"(r[2]), "=r"(r[3]) : "r"(addr));
}
__device__ __forceinline__ void mma_f32(float* d, const uint32_t* a,
                                        uint32_t b0, uint32_t b1) {
    asm volatile(
        "mma.sync.aligned.m16n8k16.row.col.f32.f16.f16.f32 "
        "{%0,%1,%2,%3}, {%4,%5,%6,%7}, {%8,%9}, {%0,%1,%2,%3};"
        : "+f"(d[0]), "+f"(d[1]), "+f"(d[2]), "+f"(d[3])
        : "r"(a[0]), "r"(a[1]), "r"(a[2]), "r"(a[3]), "r"(b0), "r"(b1));
}
__device__ __forceinline__ void mma_f16(uint32_t* d, const uint32_t* a,
                                        uint32_t b0, uint32_t b1) {
    asm volatile(
        "mma.sync.aligned.m16n8k16.row.col.f16.f16.f16.f16 "
        "{%0,%1}, {%2,%3,%4,%5}, {%6,%7}, {%0,%1};"
        : "+r"(d[0]), "+r"(d[1])
        : "r"(a[0]), "r"(a[1]), "r"(a[2]), "r"(a[3]), "r"(b0), "r"(b1));
}
__device__ __forceinline__ unsigned long long pack2(float lo, float hi) {
    unsigned long long r;
    asm("mov.b64 %0, {%1, %2};" : "=l"(r) : "f"(lo), "f"(hi));
    return r;
}
__device__ __forceinline__ void unpack2(unsigned long long v, float& lo, float& hi) {
    asm("mov.b64 {%0, %1}, %2;" : "=f"(lo), "=f"(hi) : "l"(v));
}
__device__ __forceinline__ void fma2(unsigned long long& d, unsigned long long a,
                                     unsigned long long b) {
    asm("fma.rn.f32x2 %0, %1, %2, %0;" : "+l"(d) : "l"(a), "l"(b));
}
__device__ __forceinline__ void barx(int id, int cnt) {
    asm volatile("bar.sync %0, %1;" :: "r"(id), "r"(cnt) : "memory");
}

// ---------------- prep ----------------
__global__ void prep_kernel(const float* __restrict__ f, const float* __restrict__ s) {
    int i = blockIdx.x;
    int t = threadIdx.x;  // 128
    const float* fr = f + (size_t)i * D;
    const float* sr = s + (size_t)i * D;
    __half* Ar = g_Ah + (size_t)i * KD;
    __half* Br = g_Bh + (size_t)i * KD;
    float t3p = 0.f, lsp = 0.f;
    for (int d = t; d < D; d += 128) {
        float x = fr[d], sg = sr[d];
        float inv = 1.0f / sg;
        float a1 = x * x, a2 = x, b1 = inv, b2 = -2.0f * x * inv;
        __half h;
        h = __float2half_rn(a1); Ar[d]       = h; Ar[1024 + d] = __float2half_rn(a1 - __half2float(h));
        h = __float2half_rn(a2); Ar[512 + d] = h; Ar[1536 + d] = __float2half_rn(a2 - __half2float(h));
        h = __float2half_rn(b1); Br[d]       = h; Br[1024 + d] = __float2half_rn(b1 - __half2float(h));
        h = __float2half_rn(b2); Br[512 + d] = h; Br[1536 + d] = __float2half_rn(b2 - __half2float(h));
        g_A32[(size_t)d * B2 + i] = make_float2(a1, a2);
        g_B1[(size_t)d * B2 + i]  = b1;
        g_B2[(size_t)d * B2 + i]  = b2;
        t3p += a1 * inv;
        lsp += __logf(sg);
    }
    __shared__ float sh1[128], sh2[128];
    sh1[t] = t3p; sh2[t] = lsp;
    __syncthreads();
    for (int st = 64; st > 0; st >>= 1) {
        if (t < st) { sh1[t] += sh1[t + st]; sh2[t] += sh2[t + st]; }
        __syncthreads();
    }
    if (t == 0) { g_t3[i] = sh1[0]; g_ls[i] = sh2[0]; g_rowsum[i] = 0.f; }
}

// ---------------- gt + constants ----------------
__global__ void gt_kernel(const float* __restrict__ f, const float* __restrict__ s,
                          const int* __restrict__ label) {
    int i = blockIdx.x;
    int lab = label[i];
    int pos = lab + (lab >= i ? 1 : 0);
    const float* xi = f + (size_t)i * D;
    const float* xp = f + (size_t)pos * D;
    const float* sp = s + (size_t)pos * D;
    float p = 0.f;
    for (int d = threadIdx.x; d < D; d += 256) {
        float dd = xi[d] - xp[d];
        p += dd * dd / sp[d];
    }
    __shared__ float sh[256];
    sh[threadIdx.x] = p;
    __syncthreads();
    for (int st = 128; st > 0; st >>= 1) {
        if (threadIdx.x < st) sh[threadIdx.x] += sh[threadIdx.x + st];
        __syncthreads();
    }
    if (threadIdx.x == 0) {
        g_c[i]  = 0.1f * sh[0] + 0.5f * g_ls[i];
        g_cj[i] = -0.5f * g_ls[pos] - 0.1f * g_t3[i];
    }
}

// ---------------- MMA chunk loader (256 MMA threads, mtid 0..255) --------
__device__ __forceinline__ void load_chunk(int c, int st, int i0, int j0,
                                           uint32_t sb, int mtid) {
    int acol, bcol;
    if (c < 32) { acol = c * 64; bcol = (acol + 1024) & 2047; }
    else        { acol = (c - 32) * 64; bcol = acol; }
    const uint32_t aS = sb + st * STAGE_SZ;
    const uint32_t bS = aS + A_SZ;
#pragma unroll
    for (int it = 0; it < 8; it++) {            // A: 2048 16B segs
        int id = mtid + it * 256;
        int row = id >> 3, kc = id & 7;
        cp_async16(aS + row * ROWB + kc * 16,
                   g_Ah + (size_t)(i0 + row) * KD + acol + kc * 8);
    }
#pragma unroll
    for (int it = 0; it < 3; it++) {            // B: 768 16B segs (96 rows)
        int id = mtid + it * 256;
        int row = id >> 3, kc = id & 7;
        cp_async16(bS + row * ROWB + kc * 16,
                   g_Bh + (size_t)(j0 + row) * KD + bcol + kc * 8);
    }
}

// ---------------- FMA b-block loader (128 FMA threads) ----------------
__device__ __forceinline__ void load_bblk(int blk, int buf, int j0,
                                          uint32_t sb, int ftid) {
    const uint32_t base = sb + BBASE + buf * BBLK;
#pragma unroll
    for (int it = 0; it < 16; it++) {           // bx: 2048 8B segs
        int id = ftid + it * 128;
        int dl = id >> 4, jp = id & 15;
        cp_async8(base + id * 8,
                  g_B1 + (size_t)(blk * 128 + dl) * B2 + j0 + TNM + jp * 2);
    }
#pragma unroll
    for (int it = 0; it < 16; it++) {           // by: 2048 8B segs
        int id = ftid + it * 128;
        int dl = id >> 4, jp = id & 15;
        cp_async8(base + 16384 + id * 8,
                  g_B2 + (size_t)(blk * 128 + dl) * B2 + j0 + TNM + jp * 2);
    }
}

// ---------------- main dual-pipe dist kernel ----------------
__global__ __launch_bounds__(384, 1)
void dist_kernel(float* __restrict__ out, int write_logits) {
    extern __shared__ char smem[];
    const uint32_t sb = smem_u32(smem);
    const int tid  = threadIdx.x;
    const int lane = tid & 31;
    const int wid  = tid >> 5;
    const int i0 = blockIdx.y * TM;
    const int j0 = blockIdx.x * 128;

    if (wid >= 4) {
        // ============ MMA warps (wid 4..11): cols [j0, j0+96) ============
        const int mtid = tid - 128;     // 0..255
        const int wq = wid - 4;
        const int wm = wq & 3;
        const int wn = wq >> 2;

#pragma unroll
        for (int s = 0; s < NSTG - 1; s++) { load_chunk(s, s, i0, j0, sb, mtid); cp_commit(); }

        const uint32_t aoff = (wm * 64 + (lane & 15)) * ROWB + (lane >> 4) * 16;
        const uint32_t boff = (wn * 48 + (lane & 15)) * ROWB + (lane >> 4) * 16;

        uint32_t afr[2][4][4], bfr[3][4];   // A double-buffered, B single

        // ---- phase A: cross (chunks 0..31, fp16 accum) ----
        uint32_t acch[4][6][2];
#pragma unroll
        for (int mi = 0; mi < 4; mi++)
#pragma unroll
            for (int ni = 0; ni < 6; ni++) { acch[mi][ni][0] = 0u; acch[mi][ni][1] = 0u; }

        for (int c = 0; c < 32; c++) {
            cp_wait<1>();
            barx(1, 256);
            int pf = c + NSTG - 1;
            load_chunk(pf, pf % NSTG, i0, j0, sb, mtid);
            cp_commit();

            const uint32_t aS = sb + (c % NSTG) * STAGE_SZ;
            const uint32_t bS = aS + A_SZ;
#pragma unroll
            for (int mi = 0; mi < 4; mi++) ldsm4(aS + aoff + mi * (16 * ROWB), afr[0][mi]);
#pragma unroll
            for (int ks = 0; ks < 4; ks++) {
                const int cur = ks & 1, nxt = cur ^ 1;
#pragma unroll
                for (int np = 0; np < 3; np++)
                    ldsm4(bS + boff + np * (16 * ROWB) + ks * 32, bfr[np]);
                if (ks < 3)
#pragma unroll
                    for (int mi = 0; mi < 4; mi++)
                        ldsm4(aS + aoff + mi * (16 * ROWB) + (ks + 1) * 32, afr[nxt][mi]);
#pragma unroll
                for (int mi = 0; mi < 4; mi++)
#pragma unroll
                    for (int ni = 0; ni < 6; ni++)
                        mma_f16(acch[mi][ni], afr[cur][mi],
                                bfr[ni >> 1][ni & 1], bfr[ni >> 1][(ni & 1) + 2]);
            }
        }

        float acc[4][6][4];
#pragma unroll
        for (int mi = 0; mi < 4; mi++)
#pragma unroll
            for (int ni = 0; ni < 6; ni++) {
                __half2 h0 = *(__half2*)&acch[mi][ni][0];
                __half2 h1 = *(__half2*)&acch[mi][ni][1];
                acc[mi][ni][0] = __low2float(h0);
                acc[mi][ni][1] = __high2float(h0);
                acc[mi][ni][2] = __low2float(h1);
                acc[mi][ni][3] = __high2float(h1);
            }

        // ---- phase B: hihi (chunks 32..47, fp32 accum) ----
        for (int c = 32; c < NCH; c++) {
            cp_wait<1>();
            barx(1, 256);
            int pf = c + NSTG - 1;
            if (pf < NCH) { load_chunk(pf, pf % NSTG, i0, j0, sb, mtid); cp_commit(); }

            const uint32_t aS = sb + (c % NSTG) * STAGE_SZ;
            const uint32_t bS = aS + A_SZ;
#pragma unroll
            for (int mi = 0; mi < 4; mi++) ldsm4(aS + aoff + mi * (16 * ROWB), afr[0][mi]);
#pragma unroll
            for (int ks = 0; ks < 4; ks++) {
                const int cur = ks & 1, nxt = cur ^ 1;
#pragma unroll
                for (int np = 0; np < 3; np++)
                    ldsm4(bS + boff + np * (16 * ROWB) + ks * 32, bfr[np]);
                if (ks < 3)
#pragma unroll
                    for (int mi = 0; mi < 4; mi++)
                        ldsm4(aS + aoff + mi * (16 * ROWB) + (ks + 1) * 32, afr[nxt][mi]);
#pragma unroll
                for (int mi = 0; mi < 4; mi++)
#pragma unroll
                    for (int ni = 0; ni < 6; ni++)
                        mma_f32(acc[mi][ni], afr[cur][mi],
                                bfr[ni >> 1][ni & 1], bfr[ni >> 1][(ni & 1) + 2]);
            }
        }

        // ---- MMA epilogue ----
        float cv0[4], cv1[4];
#pragma unroll
        for (int mi = 0; mi < 4; mi++) {
            int r0 = i0 + wm * 64 + mi * 16 + (lane >> 2);
            cv0[mi] = g_c[r0];
            cv1[mi] = g_c[r0 + 8];
        }
        float cjv[6][2];
#pragma unroll
        for (int ni = 0; ni < 6; ni++) {
            int cb = j0 + wn * 48 + (ni >> 1) * 16 + (ni & 1) * 8 + (lane & 3) * 2;
            cjv[ni][0] = g_cj[cb];
            cjv[ni][1] = g_cj[cb + 1];
        }
#pragma unroll
        for (int mi = 0; mi < 4; mi++) {
            const int r0 = i0 + wm * 64 + mi * 16 + (lane >> 2);
            const int r1 = r0 + 8;
            float rs0 = 0.f, rs1 = 0.f;
#pragma unroll
            for (int ni = 0; ni < 6; ni++) {
                const int cb = j0 + wn * 48 + (ni >> 1) * 16 + (ni & 1) * 8 + (lane & 3) * 2;
                float e0 = __expf(cv0[mi] + cjv[ni][0] - 0.1f * acc[mi][ni][0]);
                float e1 = __expf(cv0[mi] + cjv[ni][1] - 0.1f * acc[mi][ni][1]);
                float e2 = __expf(cv1[mi] + cjv[ni][0] - 0.1f * acc[mi][ni][2]);
                float e3 = __expf(cv1[mi] + cjv[ni][1] - 0.1f * acc[mi][ni][3]);
                if (cb     == r0) e0 = 0.f;
                if (cb + 1 == r0) e1 = 0.f;
                if (cb     == r1) e2 = 0.f;
                if (cb + 1 == r1) e3 = 0.f;
                rs0 += e0 + e1;
                rs1 += e2 + e3;
                if (write_logits) {
                    if (cb     != r0) out[(size_t)r0 * NM1 + cb     - (cb     > r0)] = e0;
                    if (cb + 1 != r0) out[(size_t)r0 * NM1 + cb + 1 - (cb + 1 > r0)] = e1;
                    if (cb     != r1) out[(size_t)r1 * NM1 + cb     - (cb     > r1)] = e2;
                    if (cb + 1 != r1) out[(size_t)r1 * NM1 + cb + 1 - (cb + 1 > r1)] = e3;
                }
            }
            rs0 += __shfl_xor_sync(0xFFFFFFFFu, rs0, 1);
            rs0 += __shfl_xor_sync(0xFFFFFFFFu, rs0, 2);
            rs1 += __shfl_xor_sync(0xFFFFFFFFu, rs1, 1);
            rs1 += __shfl_xor_sync(0xFFFFFFFFu, rs1, 2);
            if ((lane & 3) == 0) {
                atomicAdd(&g_rowsum[r0], rs0);
                atomicAdd(&g_rowsum[r1], rs1);
            }
        }
    } else {
        // ============ FMA warps (wid 0..3): cols [j0+96, j0+128), exact fp32 ============
        const int ftid = tid;             // 0..127
        const int fw   = wid;             // 0..3
        const int rA   = fw * 64 + lane;  // local rows within 256
        const int rB   = rA + 32;

        unsigned long long acc2[2][16];
#pragma unroll
        for (int r = 0; r < 2; r++)
#pragma unroll
            for (int jp = 0; jp < 16; jp++) acc2[r][jp] = 0ull;

        load_bblk(0, 0, j0, sb, ftid);
        cp_commit();

        for (int blk = 0; blk < 4; blk++) {
            if (blk + 1 < 4) { load_bblk(blk + 1, (blk + 1) & 1, j0, sb, ftid); }
            cp_commit();
            cp_wait<1>();
            barx(2, 128);

            const char* bx = smem + BBASE + (blk & 1) * BBLK;
            const char* by = bx + 16384;
            const float2* apA = g_A32 + (size_t)(blk * 128) * B2 + i0 + rA;
            const float2* apB = apA + 32;

            float2 a0 = apA[0],          a1 = apB[0];
            float2 p0 = apA[B2],         p1 = apB[B2];
#pragma unroll 4
            for (int dl = 0; dl < 128; dl++) {
                float2 n0, n1;
                if (dl + 2 < 128) {
                    n0 = apA[(size_t)(dl + 2) * B2];
                    n1 = apB[(size_t)(dl + 2) * B2];
                }
                unsigned long long axx = pack2(a0.x, a0.x);
                unsigned long long ayy = pack2(a0.y, a0.y);
                unsigned long long bxx = pack2(a1.x, a1.x);
                unsigned long long byy = pack2(a1.y, a1.y);
#pragma unroll
                for (int j2 = 0; j2 < 8; j2++) {
                    ulonglong2 vx = *(const ulonglong2*)(bx + dl * 128 + j2 * 16);
                    ulonglong2 vy = *(const ulonglong2*)(by + dl * 128 + j2 * 16);
                    fma2(acc2[0][j2 * 2],     axx, vx.x);
                    fma2(acc2[0][j2 * 2],     ayy, vy.x);
                    fma2(acc2[0][j2 * 2 + 1], axx, vx.y);
                    fma2(acc2[0][j2 * 2 + 1], ayy, vy.y);
                    fma2(acc2[1][j2 * 2],     bxx, vx.x);
                    fma2(acc2[1][j2 * 2],     byy, vy.x);
                    fma2(acc2[1][j2 * 2 + 1], bxx, vx.y);
                    fma2(acc2[1][j2 * 2 + 1], byy, vy.y);
                }
                a0 = p0; a1 = p1; p0 = n0; p1 = n1;
            }
            barx(2, 128);   // all FMA warps done with this buffer before overwrite
        }

        // ---- FMA epilogue ----
        const int igA = i0 + rA;
        const int igB = i0 + rB;
        const float cvA = g_c[igA];
        const float cvB = g_c[igB];
        float* buf = (float*)(smem + BBASE + fw * 8448);

        float rsA = 0.f, rsB = 0.f;
#pragma unroll
        for (int jp = 0; jp < 16; jp++) {
            float dA0, dA1, dB0, dB1;
            unpack2(acc2[0][jp], dA0, dA1);
            unpack2(acc2[1][jp], dB0, dB1);
            int c0 = jp * 2, c1 = jp * 2 + 1;
            int jg0 = j0 + TNM + c0, jg1 = j0 + TNM + c1;
            float cj0 = g_cj[jg0], cj1 = g_cj[jg1];
            float eA0 = __expf(cvA + cj0 - 0.1f * dA0);
            float eA1 = __expf(cvA + cj1 - 0.1f * dA1);
            float eB0 = __expf(cvB + cj0 - 0.1f * dB0);
            float eB1 = __expf(cvB + cj1 - 0.1f * dB1);
            if (jg0 == igA) eA0 = 0.f;
            if (jg1 == igA) eA1 = 0.f;
            if (jg0 == igB) eB0 = 0.f;
            if (jg1 == igB) eB1 = 0.f;
            rsA += eA0 + eA1;
            rsB += eB0 + eB1;
            buf[lane * 33 + c0]        = eA0;
            buf[lane * 33 + c1]        = eA1;
            buf[(lane + 32) * 33 + c0] = eB0;
            buf[(lane + 32) * 33 + c1] = eB1;
        }
        atomicAdd(&g_rowsum[igA], rsA);
        atomicAdd(&g_rowsum[igB], rsB);
        __syncwarp();
        if (write_logits) {
            const int jg = j0 + TNM + lane;
#pragma unroll 4
            for (int r = 0; r < 64; r++) {
                const int ig = i0 + fw * 64 + r;
                float v = buf[r * 33 + lane];
                if (jg != ig)
                    out[(size_t)ig * NM1 + jg - (jg > ig ? 1 : 0)] = v;
            }
        }
    }
}

// ---------------- loss = mean(log(rowsum)) ----------------
__global__ void loss_kernel(float* __restrict__ loss_out) {
    __shared__ float sh[1024];
    float p = 0.f;
    for (int i = threadIdx.x; i < B2; i += 1024) p += __logf(g_rowsum[i]);
    sh[threadIdx.x] = p;
    __syncthreads();
    for (int st = 512; st > 0; st >>= 1) {
        if (threadIdx.x < st) sh[threadIdx.x] += sh[threadIdx.x + st];
        __syncthreads();
    }
    if (threadIdx.x == 0) *loss_out = sh[0] / (float)B2;
}

// ---------------- launch ----------------
extern "C" void kernel_launch(void* const* d_in, const int* in_sizes, int n_in,
                              void* d_out, int out_size) {
    const float* f     = (const float*)d_in[0];
    const float* s     = (const float*)d_in[1];
    const int*   label = (const int*)d_in[2];

    float* outf = (float*)d_out;
    const long long LOGN = (long long)B2 * NM1;
    float* loss_out  = nullptr;
    float* logit_out = nullptr;
    if ((long long)out_size == LOGN + 1) { loss_out = outf; logit_out = outf + 1; }
    else if ((long long)out_size == LOGN) { logit_out = outf; }
    else { loss_out = outf; }

    cudaFuncSetAttribute(dist_kernel, cudaFuncAttributeMaxDynamicSharedMemorySize, SM_TOTAL);

    prep_kernel<<<B2, 128>>>(f, s);
    gt_kernel<<<B2, 256>>>(f, s, label);

    dim3 grid(B2 / 128, B2 / TM);
    dist_kernel<<<grid, 384, SM_TOTAL>>>(logit_out ? logit_out : outf,
                                         logit_out != nullptr ? 1 : 0);

    if (loss_out) loss_kernel<<<1, 1024>>>(loss_out);
}

// round 15
// speedup vs baseline: 1.4557x; 1.4557x over previous
#include <cuda_runtime.h>
#include <cuda_fp16.h>
#include <cstdint>

#define B2   8192
#define D    512
#define KD   2048      // fp16 cols: [0,1024) hi, [1024,2048) lo
#define NM1  8191

#define TM   256
#define TN   128
#define BK   64        // fp16 per chunk (128 B rows)
#define NSTG 3
#define NCHT 48        // chunks per tile: 32 cross (fp16 acc) + 16 hihi (fp32 acc)
#define NTOT 96        // 2 tiles per CTA

#define ROWB 144                       // 128 B data + 16 B pad
#define A_SZ (256 * ROWB)              // 36864
#define B_SZ (128 * ROWB)              // 18432
#define STAGE_SZ (A_SZ + B_SZ)         // 55296
#define SM_TOTAL (NSTG * STAGE_SZ)     // 165888

// ---------------- device scratch ----------------
__device__ __align__(128) __half g_Ah[(size_t)B2 * KD];  // [hi(x^2)|hi(x)|lo(x^2)|lo(x)]
__device__ __align__(128) __half g_Bh[(size_t)B2 * KD];  // [hi(1/s)|hi(-2x/s)|lo(1/s)|lo(-2x/s)]
__device__ float g_t3[B2];
__device__ float g_ls[B2];
__device__ float g_c[B2];      // 0.1*gt_i + 0.5*ls_i
__device__ float g_cj[B2];     // -0.5*ls[pos(j)] - 0.1*t3[j]
__device__ float g_rowsum[B2];

// ---------------- PTX helpers ----------------
__device__ __forceinline__ uint32_t smem_u32(const void* p) {
    uint32_t a;
    asm("{ .reg .u64 t; cvta.to.shared.u64 t, %1; cvt.u32.u64 %0, t; }" : "=r"(a) : "l"(p));
    return a;
}
__device__ __forceinline__ void cp_async16(uint32_t dst, const void* src) {
    asm volatile("cp.async.cg.shared.global [%0], [%1], 16;" :: "r"(dst), "l"(src) : "memory");
}
__device__ __forceinline__ void cp_commit() {
    asm volatile("cp.async.commit_group;" ::: "memory");
}
template <int N> __device__ __forceinline__ void cp_wait() {
    asm volatile("cp.async.wait_group %0;" :: "n"(N) : "memory");
}
__device__ __forceinline__ void ldsm4(uint32_t addr, uint32_t* r) {
    asm volatile("ldmatrix.sync.aligned.m8n8.x4.shared.b16 {%0,%1,%2,%3}, [%4];"
                 : "=r"(r[0]), "=r"(r[1]), "=r"(r[2]), "=r"(r[3]) : "r"(addr));
}
// fp16 x fp16 -> fp32 accum
__device__ __forceinline__ void mma_f32(float* d, const uint32_t* a,
                                        uint32_t b0, uint32_t b1) {
    asm volatile(
        "mma.sync.aligned.m16n8k16.row.col.f32.f16.f16.f32 "
        "{%0,%1,%2,%3}, {%4,%5,%6,%7}, {%8,%9}, {%0,%1,%2,%3};"
        : "+f"(d[0]), "+f"(d[1]), "+f"(d[2]), "+f"(d[3])
        : "r"(a[0]), "r"(a[1]), "r"(a[2]), "r"(a[3]), "r"(b0), "r"(b1));
}
// fp16 x fp16 -> fp16 accum
__device__ __forceinline__ void mma_f16(uint32_t* d, const uint32_t* a,
                                        uint32_t b0, uint32_t b1) {
    asm volatile(
        "mma.sync.aligned.m16n8k16.row.col.f16.f16.f16.f16 "
        "{%0,%1}, {%2,%3,%4,%5}, {%6,%7}, {%0,%1};"
        : "+r"(d[0]), "+r"(d[1])
        : "r"(a[0]), "r"(a[1]), "r"(a[2]), "r"(a[3]), "r"(b0), "r"(b1));
}

// ---------------- prep: fp16 hi/lo splits + t3 + ls ----------------
__global__ void prep_kernel(const float* __restrict__ f, const float* __restrict__ s) {
    int i = blockIdx.x;
    int t = threadIdx.x;  // 128
    const float* fr = f + (size_t)i * D;
    const float* sr = s + (size_t)i * D;
    __half* Ar = g_Ah + (size_t)i * KD;
    __half* Br = g_Bh + (size_t)i * KD;
    float t3p = 0.f, lsp = 0.f;
    for (int d = t; d < D; d += 128) {
        float x = fr[d], sg = sr[d];
        float inv = 1.0f / sg;
        float a1 = x * x, a2 = x, b1 = inv, b2 = -2.0f * x * inv;
        __half h;
        h = __float2half_rn(a1); Ar[d]       = h; Ar[1024 + d] = __float2half_rn(a1 - __half2float(h));
        h = __float2half_rn(a2); Ar[512 + d] = h; Ar[1536 + d] = __float2half_rn(a2 - __half2float(h));
        h = __float2half_rn(b1); Br[d]       = h; Br[1024 + d] = __float2half_rn(b1 - __half2float(h));
        h = __float2half_rn(b2); Br[512 + d] = h; Br[1536 + d] = __float2half_rn(b2 - __half2float(h));
        t3p += a1 * inv;
        lsp += __logf(sg);
    }
    __shared__ float sh1[128], sh2[128];
    sh1[t] = t3p; sh2[t] = lsp;
    __syncthreads();
    for (int st = 64; st > 0; st >>= 1) {
        if (t < st) { sh1[t] += sh1[t + st]; sh2[t] += sh2[t + st]; }
        __syncthreads();
    }
    if (t == 0) { g_t3[i] = sh1[0]; g_ls[i] = sh2[0]; g_rowsum[i] = 0.f; }
}

// ---------------- gt + per-row/col constants ----------------
__global__ void gt_kernel(const float* __restrict__ f, const float* __restrict__ s,
                          const int* __restrict__ label) {
    int i = blockIdx.x;
    int lab = label[i];
    int pos = lab + (lab >= i ? 1 : 0);
    const float* xi = f + (size_t)i * D;
    const float* xp = f + (size_t)pos * D;
    const float* sp = s + (size_t)pos * D;
    float p = 0.f;
    for (int d = threadIdx.x; d < D; d += 256) {
        float dd = xi[d] - xp[d];
        p += dd * dd / sp[d];
    }
    __shared__ float sh[256];
    sh[threadIdx.x] = p;
    __syncthreads();
    for (int st = 128; st > 0; st >>= 1) {
        if (threadIdx.x < st) sh[threadIdx.x] += sh[threadIdx.x + st];
        __syncthreads();
    }
    if (threadIdx.x == 0) {
        g_c[i]  = 0.1f * sh[0] + 0.5f * g_ls[i];
        g_cj[i] = -0.5f * g_ls[pos] - 0.1f * g_t3[i];
    }
}

// ---------------- chunk loader (global chunk id 0..95 over 2 tiles) --------
// per-tile chunk c%48: c<32 cross (A col c*64 in [hi|lo], B col +1024 mod 2048),
//                      c>=32 hihi (A,B cols (c-32)*64 in [0,1024))
__device__ __forceinline__ void load_chunk(int gc, int i0, int j0base, uint32_t sb) {
    const int tile = gc / NCHT;
    const int c    = gc - tile * NCHT;
    const int j0   = j0base + tile * TN;
    int acol, bcol;
    if (c < 32) { acol = c * 64; bcol = (acol + 1024) & 2047; }
    else        { acol = (c - 32) * 64; bcol = acol; }
    const uint32_t aS = sb + (gc % NSTG) * STAGE_SZ;
    const uint32_t bS = aS + A_SZ;
    const int tid = threadIdx.x;
#pragma unroll
    for (int it = 0; it < 8; it++) {            // A: 2048 16B segs
        int id = tid + it * 256;
        int row = id >> 3, kc = id & 7;
        cp_async16(aS + row * ROWB + kc * 16,
                   g_Ah + (size_t)(i0 + row) * KD + acol + kc * 8);
    }
#pragma unroll
    for (int it = 0; it < 4; it++) {            // B: 1024 16B segs
        int id = tid + it * 256;
        int row = id >> 3, kc = id & 7;
        cp_async16(bS + row * ROWB + kc * 16,
                   g_Bh + (size_t)(j0 + row) * KD + bcol + kc * 8);
    }
}

// ---------------- main dist kernel: persistent 2-tile CTA ----------------
__global__ __launch_bounds__(256)
void dist_kernel(float* __restrict__ out, int write_logits) {
    extern __shared__ char smem[];
    const uint32_t sb = smem_u32(smem);
    const int tid  = threadIdx.x;
    const int lane = tid & 31;
    const int wid  = tid >> 5;
    const int wm   = wid & 3;
    const int wn   = wid >> 2;
    const int i0     = blockIdx.y * TM;
    const int j0base = blockIdx.x * (2 * TN);

    // prologue: chunks 0,1 -> stages 0,1
#pragma unroll
    for (int s = 0; s < NSTG - 1; s++) { load_chunk(s, i0, j0base, sb); cp_commit(); }

    const uint32_t aoff = (wm * 64 + (lane & 15)) * ROWB + (lane >> 4) * 16;
    const uint32_t boff = (wn * 64 + (lane & 15)) * ROWB + (lane >> 4) * 16;

    uint32_t afr[2][4][4], bfr[2][4][4];

    for (int tile = 0; tile < 2; tile++) {
        const int gbase = tile * NCHT;
        const int j0    = j0base + tile * TN;

        // ---------------- phase A: cross (fp16 accum) ----------------
        uint32_t acch[4][8][2];
#pragma unroll
        for (int mi = 0; mi < 4; mi++)
#pragma unroll
            for (int ni = 0; ni < 8; ni++) { acch[mi][ni][0] = 0u; acch[mi][ni][1] = 0u; }

        for (int c = 0; c < 32; c++) {
            const int gc = gbase + c;
            cp_wait<1>();
            __syncthreads();
            int pf = gc + NSTG - 1;
            if (pf < NTOT) { load_chunk(pf, i0, j0base, sb); cp_commit(); }

            const uint32_t aS = sb + (gc % NSTG) * STAGE_SZ;
            const uint32_t bS = aS + A_SZ;
#pragma unroll
            for (int mi = 0; mi < 4; mi++) ldsm4(aS + aoff + mi * (16 * ROWB), afr[0][mi]);
#pragma unroll
            for (int np = 0; np < 4; np++) ldsm4(bS + boff + np * (16 * ROWB), bfr[0][np]);
#pragma unroll
            for (int ks = 0; ks < 4; ks++) {
                const int cur = ks & 1, nxt = cur ^ 1;
                if (ks < 3) {
#pragma unroll
                    for (int mi = 0; mi < 4; mi++)
                        ldsm4(aS + aoff + mi * (16 * ROWB) + (ks + 1) * 32, afr[nxt][mi]);
#pragma unroll
                    for (int np = 0; np < 4; np++)
                        ldsm4(bS + boff + np * (16 * ROWB) + (ks + 1) * 32, bfr[nxt][np]);
                }
#pragma unroll
                for (int mi = 0; mi < 4; mi++)
#pragma unroll
                    for (int ni = 0; ni < 8; ni++)
                        mma_f16(acch[mi][ni], afr[cur][mi],
                                bfr[cur][ni >> 1][ni & 1], bfr[cur][ni >> 1][(ni & 1) + 2]);
            }
        }

        // convert cross fp16 accumulators to fp32
        float acc[4][8][4];
#pragma unroll
        for (int mi = 0; mi < 4; mi++)
#pragma unroll
            for (int ni = 0; ni < 8; ni++) {
                __half2 h0 = *(__half2*)&acch[mi][ni][0];
                __half2 h1 = *(__half2*)&acch[mi][ni][1];
                acc[mi][ni][0] = __low2float(h0);
                acc[mi][ni][1] = __high2float(h0);
                acc[mi][ni][2] = __low2float(h1);
                acc[mi][ni][3] = __high2float(h1);
            }

        // ---------------- phase B: hihi (fp32 accum) ----------------
        for (int c = 32; c < NCHT; c++) {
            const int gc = gbase + c;
            cp_wait<1>();
            __syncthreads();
            int pf = gc + NSTG - 1;
            if (pf < NTOT) { load_chunk(pf, i0, j0base, sb); cp_commit(); }

            const uint32_t aS = sb + (gc % NSTG) * STAGE_SZ;
            const uint32_t bS = aS + A_SZ;
#pragma unroll
            for (int mi = 0; mi < 4; mi++) ldsm4(aS + aoff + mi * (16 * ROWB), afr[0][mi]);
#pragma unroll
            for (int np = 0; np < 4; np++) ldsm4(bS + boff + np * (16 * ROWB), bfr[0][np]);
#pragma unroll
            for (int ks = 0; ks < 4; ks++) {
                const int cur = ks & 1, nxt = cur ^ 1;
                if (ks < 3) {
#pragma unroll
                    for (int mi = 0; mi < 4; mi++)
                        ldsm4(aS + aoff + mi * (16 * ROWB) + (ks + 1) * 32, afr[nxt][mi]);
#pragma unroll
                    for (int np = 0; np < 4; np++)
                        ldsm4(bS + boff + np * (16 * ROWB) + (ks + 1) * 32, bfr[nxt][np]);
                }
#pragma unroll
                for (int mi = 0; mi < 4; mi++)
#pragma unroll
                    for (int ni = 0; ni < 8; ni++)
                        mma_f32(acc[mi][ni], afr[cur][mi],
                                bfr[cur][ni >> 1][ni & 1], bfr[cur][ni >> 1][(ni & 1) + 2]);
            }
        }

        // ---------------- epilogue (tile-1 loads already in flight) ----------------
        float cv0[4], cv1[4];
#pragma unroll
        for (int mi = 0; mi < 4; mi++) {
            int r0 = i0 + wm * 64 + mi * 16 + (lane >> 2);
            cv0[mi] = g_c[r0];
            cv1[mi] = g_c[r0 + 8];
        }
        float cjv[8][2];
#pragma unroll
        for (int ni = 0; ni < 8; ni++) {
            int cb = j0 + wn * 64 + (ni >> 1) * 16 + (ni & 1) * 8 + (lane & 3) * 2;
            cjv[ni][0] = g_cj[cb];
            cjv[ni][1] = g_cj[cb + 1];
        }

#pragma unroll
        for (int mi = 0; mi < 4; mi++) {
            const int r0 = i0 + wm * 64 + mi * 16 + (lane >> 2);
            const int r1 = r0 + 8;
            float rs0 = 0.f, rs1 = 0.f;
#pragma unroll
            for (int ni = 0; ni < 8; ni++) {
                const int cb = j0 + wn * 64 + (ni >> 1) * 16 + (ni & 1) * 8 + (lane & 3) * 2;
                float e0 = __expf(cv0[mi] + cjv[ni][0] - 0.1f * acc[mi][ni][0]);
                float e1 = __expf(cv0[mi] + cjv[ni][1] - 0.1f * acc[mi][ni][1]);
                float e2 = __expf(cv1[mi] + cjv[ni][0] - 0.1f * acc[mi][ni][2]);
                float e3 = __expf(cv1[mi] + cjv[ni][1] - 0.1f * acc[mi][ni][3]);
                if (cb     == r0) e0 = 0.f;
                if (cb + 1 == r0) e1 = 0.f;
                if (cb     == r1) e2 = 0.f;
                if (cb + 1 == r1) e3 = 0.f;
                rs0 += e0 + e1;
                rs1 += e2 + e3;
                if (write_logits) {
                    if (cb     != r0) out[(size_t)r0 * NM1 + cb     - (cb     > r0)] = e0;
                    if (cb + 1 != r0) out[(size_t)r0 * NM1 + cb + 1 - (cb + 1 > r0)] = e1;
                    if (cb     != r1) out[(size_t)r1 * NM1 + cb     - (cb     > r1)] = e2;
                    if (cb + 1 != r1) out[(size_t)r1 * NM1 + cb + 1 - (cb + 1 > r1)] = e3;
                }
            }
            rs0 += __shfl_xor_sync(0xFFFFFFFFu, rs0, 1);
            rs0 += __shfl_xor_sync(0xFFFFFFFFu, rs0, 2);
            rs1 += __shfl_xor_sync(0xFFFFFFFFu, rs1, 1);
            rs1 += __shfl_xor_sync(0xFFFFFFFFu, rs1, 2);
            if ((lane & 3) == 0) {
                atomicAdd(&g_rowsum[r0], rs0);
                atomicAdd(&g_rowsum[r1], rs1);
            }
        }
    }
}

// ---------------- loss = mean(log(rowsum)) ----------------
__global__ void loss_kernel(float* __restrict__ loss_out) {
    __shared__ float sh[1024];
    float p = 0.f;
    for (int i = threadIdx.x; i < B2; i += 1024) p += __logf(g_rowsum[i]);
    sh[threadIdx.x] = p;
    __syncthreads();
    for (int st = 512; st > 0; st >>= 1) {
        if (threadIdx.x < st) sh[threadIdx.x] += sh[threadIdx.x + st];
        __syncthreads();
    }
    if (threadIdx.x == 0) *loss_out = sh[0] / (float)B2;
}

// ---------------- launch ----------------
extern "C" void kernel_launch(void* const* d_in, const int* in_sizes, int n_in,
                              void* d_out, int out_size) {
    const float* f     = (const float*)d_in[0];
    const float* s     = (const float*)d_in[1];
    const int*   label = (const int*)d_in[2];

    float* outf = (float*)d_out;
    const long long LOGN = (long long)B2 * NM1;
    float* loss_out  = nullptr;
    float* logit_out = nullptr;
    if ((long long)out_size == LOGN + 1) { loss_out = outf; logit_out = outf + 1; }
    else if ((long long)out_size == LOGN) { logit_out = outf; }
    else { loss_out = outf; }

    cudaFuncSetAttribute(dist_kernel, cudaFuncAttributeMaxDynamicSharedMemorySize, SM_TOTAL);

    prep_kernel<<<B2, 128>>>(f, s);
    gt_kernel<<<B2, 256>>>(f, s, label);

    dim3 grid(B2 / (2 * TN), B2 / TM);
    dist_kernel<<<grid, 256, SM_TOTAL>>>(logit_out ? logit_out : outf,
                                         logit_out != nullptr ? 1 : 0);

    if (loss_out) loss_kernel<<<1, 1024>>>(loss_out);
}

// round 16
// speedup vs baseline: 1.5506x; 1.0652x over previous
#include <cuda_runtime.h>
#include <cuda_fp16.h>
#include <cuda_fp8.h>
#include <cstdint>

#define B2   8192
#define D    512
#define NM1  8191

#define TM   256
#define TN   128
#define NSTG 3
#define NCH  32        // 16 fp8 cross chunks (K=2048 B) + 16 fp16 hihi chunks (K=1024)

#define ROWB 144                       // 128 B data + 16 B pad
#define A_SZ (256 * ROWB)              // 36864
#define B_SZ (128 * ROWB)              // 18432
#define STAGE_SZ (A_SZ + B_SZ)         // 55296
#define SM_TOTAL (NSTG * STAGE_SZ)     // 165888

#define LO_SCALE   1024.0f             // 2^10: lift lo out of fp8 subnormal range
#define LO_UNSCALE (1.0f / 1024.0f)

// ---------------- device scratch ----------------
__device__ __align__(128) __half g_Ah[(size_t)B2 * 1024];  // [hi(x^2)|hi(x)]       2048 B/row
__device__ __align__(128) __half g_Bh[(size_t)B2 * 1024];  // [hi(1/s)|hi(-2x/s)]   2048 B/row
__device__ __align__(128) uint8_t g_A8[(size_t)B2 * 2048]; // [q(hiA2)|q(hiA1)|q(loA2*2^10)|q(loA1*2^10)]
__device__ __align__(128) uint8_t g_B8[(size_t)B2 * 2048]; // [q(loB1*2^10)|q(loB2*2^10)|q(hiB1)|q(hiB2)]
__device__ float g_t3[B2];
__device__ float g_ls[B2];
__device__ float g_c[B2];      // 0.1*gt_i + 0.5*ls_i
__device__ float g_cj[B2];     // -0.5*ls[pos(j)] - 0.1*t3[j]
__device__ float g_rowsum[B2];

// ---------------- PTX helpers ----------------
__device__ __forceinline__ uint32_t smem_u32(const void* p) {
    uint32_t a;
    asm("{ .reg .u64 t; cvta.to.shared.u64 t, %1; cvt.u32.u64 %0, t; }" : "=r"(a) : "l"(p));
    return a;
}
__device__ __forceinline__ void cp_async16(uint32_t dst, const void* src) {
    asm volatile("cp.async.cg.shared.global [%0], [%1], 16;" :: "r"(dst), "l"(src) : "memory");
}
__device__ __forceinline__ void cp_commit() {
    asm volatile("cp.async.commit_group;" ::: "memory");
}
template <int N> __device__ __forceinline__ void cp_wait() {
    asm volatile("cp.async.wait_group %0;" :: "n"(N) : "memory");
}
__device__ __forceinline__ void ldsm4(uint32_t addr, uint32_t* r) {
    asm volatile("ldmatrix.sync.aligned.m8n8.x4.shared.b16 {%0,%1,%2,%3}, [%4];"
                 : "=r"(r[0]), "=r"(r[1]), "=r"(r[2]), "=r"(r[3]) : "r"(addr));
}
// fp16 x fp16 -> fp32 accum (k16)
__device__ __forceinline__ void mma_f32(float* d, const uint32_t* a,
                                        uint32_t b0, uint32_t b1) {
    asm volatile(
        "mma.sync.aligned.m16n8k16.row.col.f32.f16.f16.f32 "
        "{%0,%1,%2,%3}, {%4,%5,%6,%7}, {%8,%9}, {%0,%1,%2,%3};"
        : "+f"(d[0]), "+f"(d[1]), "+f"(d[2]), "+f"(d[3])
        : "r"(a[0]), "r"(a[1]), "r"(a[2]), "r"(a[3]), "r"(b0), "r"(b1));
}
// e4m3 x e4m3 -> fp32 accum (k32) — same byte geometry per k-step as f16 k16
__device__ __forceinline__ void mma_fp8(float* d, const uint32_t* a,
                                        uint32_t b0, uint32_t b1) {
    asm volatile(
        "mma.sync.aligned.m16n8k32.row.col.f32.e4m3.e4m3.f32 "
        "{%0,%1,%2,%3}, {%4,%5,%6,%7}, {%8,%9}, {%0,%1,%2,%3};"
        : "+f"(d[0]), "+f"(d[1]), "+f"(d[2]), "+f"(d[3])
        : "r"(a[0]), "r"(a[1]), "r"(a[2]), "r"(a[3]), "r"(b0), "r"(b1));
}

__device__ __forceinline__ uint8_t to_fp8(float v) {
    __nv_fp8_e4m3 q(v);
    return *(uint8_t*)&q;
}

// ---------------- prep: fp16 hi + fp8 hi/lo + t3 + ls ----------------
__global__ void prep_kernel(const float* __restrict__ f, const float* __restrict__ s) {
    int i = blockIdx.x;
    int t = threadIdx.x;  // 128
    const float* fr = f + (size_t)i * D;
    const float* sr = s + (size_t)i * D;
    __half*  Ah = g_Ah + (size_t)i * 1024;
    __half*  Bh = g_Bh + (size_t)i * 1024;
    uint8_t* A8 = g_A8 + (size_t)i * 2048;
    uint8_t* B8 = g_B8 + (size_t)i * 2048;
    float t3p = 0.f, lsp = 0.f;
    for (int d = t; d < D; d += 128) {
        float x = fr[d], sg = sr[d];
        float inv = 1.0f / sg;
        float a1 = x * x, a2 = x, b1 = inv, b2 = -2.0f * x * inv;
        __half h; float hf, lo;
        // A side: [q(hi a1)|q(hi a2)|q(lo a1*S)|q(lo a2*S)]
        h = __float2half_rn(a1); hf = __half2float(h); lo = a1 - hf;
        Ah[d] = h;        A8[d]        = to_fp8(hf); A8[1024 + d] = to_fp8(lo * LO_SCALE);
        h = __float2half_rn(a2); hf = __half2float(h); lo = a2 - hf;
        Ah[512 + d] = h;  A8[512 + d]  = to_fp8(hf); A8[1536 + d] = to_fp8(lo * LO_SCALE);
        // B side: [q(lo b1*S)|q(lo b2*S)|q(hi b1)|q(hi b2)]
        h = __float2half_rn(b1); hf = __half2float(h); lo = b1 - hf;
        Bh[d] = h;        B8[1024 + d] = to_fp8(hf); B8[d]        = to_fp8(lo * LO_SCALE);
        h = __float2half_rn(b2); hf = __half2float(h); lo = b2 - hf;
        Bh[512 + d] = h;  B8[1536 + d] = to_fp8(hf); B8[512 + d]  = to_fp8(lo * LO_SCALE);
        t3p += a1 * inv;
        lsp += __logf(sg);
    }
    __shared__ float sh1[128], sh2[128];
    sh1[t] = t3p; sh2[t] = lsp;
    __syncthreads();
    for (int st = 64; st > 0; st >>= 1) {
        if (t < st) { sh1[t] += sh1[t + st]; sh2[t] += sh2[t + st]; }
        __syncthreads();
    }
    if (t == 0) { g_t3[i] = sh1[0]; g_ls[i] = sh2[0]; g_rowsum[i] = 0.f; }
}

// ---------------- gt + per-row/col constants ----------------
__global__ void gt_kernel(const float* __restrict__ f, const float* __restrict__ s,
                          const int* __restrict__ label) {
    int i = blockIdx.x;
    int lab = label[i];
    int pos = lab + (lab >= i ? 1 : 0);
    const float* xi = f + (size_t)i * D;
    const float* xp = f + (size_t)pos * D;
    const float* sp = s + (size_t)pos * D;
    float p = 0.f;
    for (int d = threadIdx.x; d < D; d += 256) {
        float dd = xi[d] - xp[d];
        p += dd * dd / sp[d];
    }
    __shared__ float sh[256];
    sh[threadIdx.x] = p;
    __syncthreads();
    for (int st = 128; st > 0; st >>= 1) {
        if (threadIdx.x < st) sh[threadIdx.x] += sh[threadIdx.x + st];
        __syncthreads();
    }
    if (threadIdx.x == 0) {
        g_c[i]  = 0.1f * sh[0] + 0.5f * g_ls[i];
        g_cj[i] = -0.5f * g_ls[pos] - 0.1f * g_t3[i];
    }
}

// ---------------- chunk loader: 128 B per row per chunk ----------------
// chunks 0..15:  fp8 cross — byte col c*128 in A8/B8 ([hiA|loA] vs [loB|hiB])
// chunks 16..31: fp16 hihi — fp16 col (c-16)*64 in Ah/Bh (rows are 2048 B both ways)
__device__ __forceinline__ void load_chunk(int c, int st, int i0, int j0, uint32_t sb) {
    const uint8_t* baseA = (c < 16) ? g_A8 : (const uint8_t*)g_Ah;
    const uint8_t* baseB = (c < 16) ? g_B8 : (const uint8_t*)g_Bh;
    const int col = (c & 15) * 128;             // byte column within 2048 B row
    const uint32_t aS = sb + st * STAGE_SZ;
    const uint32_t bS = aS + A_SZ;
    const int tid = threadIdx.x;
#pragma unroll
    for (int it = 0; it < 8; it++) {            // A: 2048 16B segs
        int id = tid + it * 256;
        int row = id >> 3, kc = id & 7;
        cp_async16(aS + row * ROWB + kc * 16,
                   baseA + (size_t)(i0 + row) * 2048 + col + kc * 16);
    }
#pragma unroll
    for (int it = 0; it < 4; it++) {            // B: 1024 16B segs
        int id = tid + it * 256;
        int row = id >> 3, kc = id & 7;
        cp_async16(bS + row * ROWB + kc * 16,
                   baseB + (size_t)(j0 + row) * 2048 + col + kc * 16);
    }
}

// ---------------- main dist kernel: fp8 cross + fp16 hihi ----------------
__global__ __launch_bounds__(256)
void dist_kernel(float* __restrict__ out, int write_logits) {
    extern __shared__ char smem[];
    const uint32_t sb = smem_u32(smem);
    const int tid  = threadIdx.x;
    const int lane = tid & 31;
    const int wid  = tid >> 5;
    const int wm   = wid & 3;
    const int wn   = wid >> 2;
    const int i0 = blockIdx.y * TM;
    const int j0 = blockIdx.x * TN;

    // prologue: stages 0,1
#pragma unroll
    for (int s = 0; s < NSTG - 1; s++) { load_chunk(s, s, i0, j0, sb); cp_commit(); }

    const uint32_t aoff = (wm * 64 + (lane & 15)) * ROWB + (lane >> 4) * 16;
    const uint32_t boff = (wn * 64 + (lane & 15)) * ROWB + (lane >> 4) * 16;

    uint32_t afr[2][4][4], bfr[2][4][4];

    float acc[4][8][4];
#pragma unroll
    for (int mi = 0; mi < 4; mi++)
#pragma unroll
        for (int ni = 0; ni < 8; ni++)
#pragma unroll
            for (int q = 0; q < 4; q++) acc[mi][ni][q] = 0.f;

    // ---------------- phase A: fp8 cross (chunks 0..15) ----------------
    for (int c = 0; c < 16; c++) {
        cp_wait<1>();
        __syncthreads();
        int pf = c + NSTG - 1;
        load_chunk(pf, pf % NSTG, i0, j0, sb);
        cp_commit();

        const uint32_t aS = sb + (c % NSTG) * STAGE_SZ;
        const uint32_t bS = aS + A_SZ;
#pragma unroll
        for (int mi = 0; mi < 4; mi++) ldsm4(aS + aoff + mi * (16 * ROWB), afr[0][mi]);
#pragma unroll
        for (int np = 0; np < 4; np++) ldsm4(bS + boff + np * (16 * ROWB), bfr[0][np]);
#pragma unroll
        for (int ks = 0; ks < 4; ks++) {       // 4 x k32 (32 B each)
            const int cur = ks & 1, nxt = cur ^ 1;
            if (ks < 3) {
#pragma unroll
                for (int mi = 0; mi < 4; mi++)
                    ldsm4(aS + aoff + mi * (16 * ROWB) + (ks + 1) * 32, afr[nxt][mi]);
#pragma unroll
                for (int np = 0; np < 4; np++)
                    ldsm4(bS + boff + np * (16 * ROWB) + (ks + 1) * 32, bfr[nxt][np]);
            }
#pragma unroll
            for (int mi = 0; mi < 4; mi++)
#pragma unroll
                for (int ni = 0; ni < 8; ni++)
                    mma_fp8(acc[mi][ni], afr[cur][mi],
                            bfr[cur][ni >> 1][ni & 1], bfr[cur][ni >> 1][(ni & 1) + 2]);
        }
    }

    // un-scale the cross term (lo operands were pre-scaled by 2^10)
#pragma unroll
    for (int mi = 0; mi < 4; mi++)
#pragma unroll
        for (int ni = 0; ni < 8; ni++)
#pragma unroll
            for (int q = 0; q < 4; q++) acc[mi][ni][q] *= LO_UNSCALE;

    // ---------------- phase B: fp16 hihi (chunks 16..31) ----------------
    for (int c = 16; c < NCH; c++) {
        cp_wait<1>();
        __syncthreads();
        int pf = c + NSTG - 1;
        if (pf < NCH) { load_chunk(pf, pf % NSTG, i0, j0, sb); cp_commit(); }

        const uint32_t aS = sb + (c % NSTG) * STAGE_SZ;
        const uint32_t bS = aS + A_SZ;
#pragma unroll
        for (int mi = 0; mi < 4; mi++) ldsm4(aS + aoff + mi * (16 * ROWB), afr[0][mi]);
#pragma unroll
        for (int np = 0; np < 4; np++) ldsm4(bS + boff + np * (16 * ROWB), bfr[0][np]);
#pragma unroll
        for (int ks = 0; ks < 4; ks++) {       // 4 x k16 (32 B each)
            const int cur = ks & 1, nxt = cur ^ 1;
            if (ks < 3) {
#pragma unroll
                for (int mi = 0; mi < 4; mi++)
                    ldsm4(aS + aoff + mi * (16 * ROWB) + (ks + 1) * 32, afr[nxt][mi]);
#pragma unroll
                for (int np = 0; np < 4; np++)
                    ldsm4(bS + boff + np * (16 * ROWB) + (ks + 1) * 32, bfr[nxt][np]);
            }
#pragma unroll
            for (int mi = 0; mi < 4; mi++)
#pragma unroll
                for (int ni = 0; ni < 8; ni++)
                    mma_f32(acc[mi][ni], afr[cur][mi],
                            bfr[cur][ni >> 1][ni & 1], bfr[cur][ni >> 1][(ni & 1) + 2]);
        }
    }

    // ---------------- epilogue ----------------
    float cv0[4], cv1[4];
#pragma unroll
    for (int mi = 0; mi < 4; mi++) {
        int r0 = i0 + wm * 64 + mi * 16 + (lane >> 2);
        cv0[mi] = g_c[r0];
        cv1[mi] = g_c[r0 + 8];
    }
    float cjv[8][2];
#pragma unroll
    for (int ni = 0; ni < 8; ni++) {
        int cb = j0 + wn * 64 + (ni >> 1) * 16 + (ni & 1) * 8 + (lane & 3) * 2;
        cjv[ni][0] = g_cj[cb];
        cjv[ni][1] = g_cj[cb + 1];
    }

#pragma unroll
    for (int mi = 0; mi < 4; mi++) {
        const int r0 = i0 + wm * 64 + mi * 16 + (lane >> 2);
        const int r1 = r0 + 8;
        float rs0 = 0.f, rs1 = 0.f;
#pragma unroll
        for (int ni = 0; ni < 8; ni++) {
            const int cb = j0 + wn * 64 + (ni >> 1) * 16 + (ni & 1) * 8 + (lane & 3) * 2;
            float e0 = __expf(cv0[mi] + cjv[ni][0] - 0.1f * acc[mi][ni][0]);
            float e1 = __expf(cv0[mi] + cjv[ni][1] - 0.1f * acc[mi][ni][1]);
            float e2 = __expf(cv1[mi] + cjv[ni][0] - 0.1f * acc[mi][ni][2]);
            float e3 = __expf(cv1[mi] + cjv[ni][1] - 0.1f * acc[mi][ni][3]);
            if (cb     == r0) e0 = 0.f;
            if (cb + 1 == r0) e1 = 0.f;
            if (cb     == r1) e2 = 0.f;
            if (cb + 1 == r1) e3 = 0.f;
            rs0 += e0 + e1;
            rs1 += e2 + e3;
            if (write_logits) {
                if (cb     != r0) out[(size_t)r0 * NM1 + cb     - (cb     > r0)] = e0;
                if (cb + 1 != r0) out[(size_t)r0 * NM1 + cb + 1 - (cb + 1 > r0)] = e1;
                if (cb     != r1) out[(size_t)r1 * NM1 + cb     - (cb     > r1)] = e2;
                if (cb + 1 != r1) out[(size_t)r1 * NM1 + cb + 1 - (cb + 1 > r1)] = e3;
            }
        }
        rs0 += __shfl_xor_sync(0xFFFFFFFFu, rs0, 1);
        rs0 += __shfl_xor_sync(0xFFFFFFFFu, rs0, 2);
        rs1 += __shfl_xor_sync(0xFFFFFFFFu, rs1, 1);
        rs1 += __shfl_xor_sync(0xFFFFFFFFu, rs1, 2);
        if ((lane & 3) == 0) {
            atomicAdd(&g_rowsum[r0], rs0);
            atomicAdd(&g_rowsum[r1], rs1);
        }
    }
}

// ---------------- loss = mean(log(rowsum)) ----------------
__global__ void loss_kernel(float* __restrict__ loss_out) {
    __shared__ float sh[1024];
    float p = 0.f;
    for (int i = threadIdx.x; i < B2; i += 1024) p += __logf(g_rowsum[i]);
    sh[threadIdx.x] = p;
    __syncthreads();
    for (int st = 512; st > 0; st >>= 1) {
        if (threadIdx.x < st) sh[threadIdx.x] += sh[threadIdx.x + st];
        __syncthreads();
    }
    if (threadIdx.x == 0) *loss_out = sh[0] / (float)B2;
}

// ---------------- launch ----------------
extern "C" void kernel_launch(void* const* d_in, const int* in_sizes, int n_in,
                              void* d_out, int out_size) {
    const float* f     = (const float*)d_in[0];
    const float* s     = (const float*)d_in[1];
    const int*   label = (const int*)d_in[2];

    float* outf = (float*)d_out;
    const long long LOGN = (long long)B2 * NM1;
    float* loss_out  = nullptr;
    float* logit_out = nullptr;
    if ((long long)out_size == LOGN + 1) { loss_out = outf; logit_out = outf + 1; }
    else if ((long long)out_size == LOGN) { logit_out = outf; }
    else { loss_out = outf; }

    cudaFuncSetAttribute(dist_kernel, cudaFuncAttributeMaxDynamicSharedMemorySize, SM_TOTAL);

    prep_kernel<<<B2, 128>>>(f, s);
    gt_kernel<<<B2, 256>>>(f, s, label);

    dim3 grid(B2 / TN, B2 / TM);
    dist_kernel<<<grid, 256, SM_TOTAL>>>(logit_out ? logit_out : outf,
                                         logit_out != nullptr ? 1 : 0);

    if (loss_out) loss_kernel<<<1, 1024>>>(loss_out);
}

// round 17
// speedup vs baseline: 1.6064x; 1.0360x over previous
#include <cuda_runtime.h>
#include <cuda_fp16.h>
#include <cuda_fp8.h>
#include <cstdint>

#define B2   8192
#define D    512
#define NM1  8191

#define TM   128
#define TN   128
#define NSTG 3
#define NCH  32        // 16 fp8 cross chunks (K=2048 B) + 16 fp16 hihi chunks (K=1024)

#define ROWB 144                       // 128 B data + 16 B pad
#define A_SZ (128 * ROWB)              // 18432
#define B_SZ (128 * ROWB)              // 18432
#define STAGE_SZ (A_SZ + B_SZ)         // 36864
#define SM_TOTAL (NSTG * STAGE_SZ)     // 110592  -> 2 CTAs/SM

#define LO_SCALE   1024.0f             // 2^10: lift lo out of fp8 subnormal range
#define LO_UNSCALE (1.0f / 1024.0f)

// ---------------- device scratch ----------------
__device__ __align__(128) __half g_Ah[(size_t)B2 * 1024];  // [hi(x^2)|hi(x)]       2048 B/row
__device__ __align__(128) __half g_Bh[(size_t)B2 * 1024];  // [hi(1/s)|hi(-2x/s)]   2048 B/row
__device__ __align__(128) uint8_t g_A8[(size_t)B2 * 2048]; // [q(hiA2)|q(hiA1)|q(loA2*S)|q(loA1*S)]
__device__ __align__(128) uint8_t g_B8[(size_t)B2 * 2048]; // [q(loB1*S)|q(loB2*S)|q(hiB1)|q(hiB2)]
__device__ float g_t3[B2];
__device__ float g_ls[B2];
__device__ float g_c[B2];      // 0.1*gt_i + 0.5*ls_i
__device__ float g_cj[B2];     // -0.5*ls[pos(j)] - 0.1*t3[j]
__device__ float g_rowsum[B2];

// ---------------- PTX helpers ----------------
__device__ __forceinline__ uint32_t smem_u32(const void* p) {
    uint32_t a;
    asm("{ .reg .u64 t; cvta.to.shared.u64 t, %1; cvt.u32.u64 %0, t; }" : "=r"(a) : "l"(p));
    return a;
}
__device__ __forceinline__ void cp_async16(uint32_t dst, const void* src) {
    asm volatile("cp.async.cg.shared.global [%0], [%1], 16;" :: "r"(dst), "l"(src) : "memory");
}
__device__ __forceinline__ void cp_commit() {
    asm volatile("cp.async.commit_group;" ::: "memory");
}
template <int N> __device__ __forceinline__ void cp_wait() {
    asm volatile("cp.async.wait_group %0;" :: "n"(N) : "memory");
}
__device__ __forceinline__ void ldsm4(uint32_t addr, uint32_t* r) {
    asm volatile("ldmatrix.sync.aligned.m8n8.x4.shared.b16 {%0,%1,%2,%3}, [%4];"
                 : "=r"(r[0]), "=r"(r[1]), "=r"(r[2]), "=r"(r[3]) : "r"(addr));
}
// fp16 x fp16 -> fp32 accum (k16)
__device__ __forceinline__ void mma_f32(float* d, const uint32_t* a,
                                        uint32_t b0, uint32_t b1) {
    asm volatile(
        "mma.sync.aligned.m16n8k16.row.col.f32.f16.f16.f32 "
        "{%0,%1,%2,%3}, {%4,%5,%6,%7}, {%8,%9}, {%0,%1,%2,%3};"
        : "+f"(d[0]), "+f"(d[1]), "+f"(d[2]), "+f"(d[3])
        : "r"(a[0]), "r"(a[1]), "r"(a[2]), "r"(a[3]), "r"(b0), "r"(b1));
}
// e4m3 x e4m3 -> fp32 accum (k32)
__device__ __forceinline__ void mma_fp8(float* d, const uint32_t* a,
                                        uint32_t b0, uint32_t b1) {
    asm volatile(
        "mma.sync.aligned.m16n8k32.row.col.f32.e4m3.e4m3.f32 "
        "{%0,%1,%2,%3}, {%4,%5,%6,%7}, {%8,%9}, {%0,%1,%2,%3};"
        : "+f"(d[0]), "+f"(d[1]), "+f"(d[2]), "+f"(d[3])
        : "r"(a[0]), "r"(a[1]), "r"(a[2]), "r"(a[3]), "r"(b0), "r"(b1));
}

__device__ __forceinline__ uint8_t to_fp8(float v) {
    __nv_fp8_e4m3 q(v);
    return *(uint8_t*)&q;
}

// ---------------- prep: fp16 hi + fp8 hi/lo + t3 + ls ----------------
__global__ void prep_kernel(const float* __restrict__ f, const float* __restrict__ s) {
    int i = blockIdx.x;
    int t = threadIdx.x;  // 128
    const float* fr = f + (size_t)i * D;
    const float* sr = s + (size_t)i * D;
    __half*  Ah = g_Ah + (size_t)i * 1024;
    __half*  Bh = g_Bh + (size_t)i * 1024;
    uint8_t* A8 = g_A8 + (size_t)i * 2048;
    uint8_t* B8 = g_B8 + (size_t)i * 2048;
    float t3p = 0.f, lsp = 0.f;
    for (int d = t; d < D; d += 128) {
        float x = fr[d], sg = sr[d];
        float inv = 1.0f / sg;
        float a1 = x * x, a2 = x, b1 = inv, b2 = -2.0f * x * inv;
        __half h; float hf, lo;
        h = __float2half_rn(a1); hf = __half2float(h); lo = a1 - hf;
        Ah[d] = h;        A8[d]        = to_fp8(hf); A8[1024 + d] = to_fp8(lo * LO_SCALE);
        h = __float2half_rn(a2); hf = __half2float(h); lo = a2 - hf;
        Ah[512 + d] = h;  A8[512 + d]  = to_fp8(hf); A8[1536 + d] = to_fp8(lo * LO_SCALE);
        h = __float2half_rn(b1); hf = __half2float(h); lo = b1 - hf;
        Bh[d] = h;        B8[1024 + d] = to_fp8(hf); B8[d]        = to_fp8(lo * LO_SCALE);
        h = __float2half_rn(b2); hf = __half2float(h); lo = b2 - hf;
        Bh[512 + d] = h;  B8[1536 + d] = to_fp8(hf); B8[512 + d]  = to_fp8(lo * LO_SCALE);
        t3p += a1 * inv;
        lsp += __logf(sg);
    }
    __shared__ float sh1[128], sh2[128];
    sh1[t] = t3p; sh2[t] = lsp;
    __syncthreads();
    for (int st = 64; st > 0; st >>= 1) {
        if (t < st) { sh1[t] += sh1[t + st]; sh2[t] += sh2[t + st]; }
        __syncthreads();
    }
    if (t == 0) { g_t3[i] = sh1[0]; g_ls[i] = sh2[0]; g_rowsum[i] = 0.f; }
}

// ---------------- gt + per-row/col constants ----------------
__global__ void gt_kernel(const float* __restrict__ f, const float* __restrict__ s,
                          const int* __restrict__ label) {
    int i = blockIdx.x;
    int lab = label[i];
    int pos = lab + (lab >= i ? 1 : 0);
    const float* xi = f + (size_t)i * D;
    const float* xp = f + (size_t)pos * D;
    const float* sp = s + (size_t)pos * D;
    float p = 0.f;
    for (int d = threadIdx.x; d < D; d += 256) {
        float dd = xi[d] - xp[d];
        p += dd * dd / sp[d];
    }
    __shared__ float sh[256];
    sh[threadIdx.x] = p;
    __syncthreads();
    for (int st = 128; st > 0; st >>= 1) {
        if (threadIdx.x < st) sh[threadIdx.x] += sh[threadIdx.x + st];
        __syncthreads();
    }
    if (threadIdx.x == 0) {
        g_c[i]  = 0.1f * sh[0] + 0.5f * g_ls[i];
        g_cj[i] = -0.5f * g_ls[pos] - 0.1f * g_t3[i];
    }
}

// ---------------- chunk loader: 128 B per row per chunk (128 threads) ------
// chunks 0..15:  fp8 cross — byte col c*128 in A8/B8
// chunks 16..31: fp16 hihi — byte col (c&15)*128 in Ah/Bh (2048 B rows both)
__device__ __forceinline__ void load_chunk(int c, int st, int i0, int j0, uint32_t sb) {
    const uint8_t* baseA = (c < 16) ? g_A8 : (const uint8_t*)g_Ah;
    const uint8_t* baseB = (c < 16) ? g_B8 : (const uint8_t*)g_Bh;
    const int col = (c & 15) * 128;
    const uint32_t aS = sb + st * STAGE_SZ;
    const uint32_t bS = aS + A_SZ;
    const int tid = threadIdx.x;
#pragma unroll
    for (int it = 0; it < 8; it++) {            // A: 1024 16B segs (128 rows)
        int id = tid + it * 128;
        int row = id >> 3, kc = id & 7;
        cp_async16(aS + row * ROWB + kc * 16,
                   baseA + (size_t)(i0 + row) * 2048 + col + kc * 16);
    }
#pragma unroll
    for (int it = 0; it < 8; it++) {            // B: 1024 16B segs (128 rows)
        int id = tid + it * 128;
        int row = id >> 3, kc = id & 7;
        cp_async16(bS + row * ROWB + kc * 16,
                   baseB + (size_t)(j0 + row) * 2048 + col + kc * 16);
    }
}

// ---------------- main dist kernel: 128x128 tile, 2 CTAs/SM ----------------
__global__ __launch_bounds__(128, 2)
void dist_kernel(float* __restrict__ out, int write_logits) {
    extern __shared__ char smem[];
    const uint32_t sb = smem_u32(smem);
    const int tid  = threadIdx.x;
    const int lane = tid & 31;
    const int wid  = tid >> 5;      // 0..3
    const int wm   = wid & 1;       // 2 M groups of 64
    const int wn   = wid >> 1;      // 2 N groups of 64
    const int i0 = blockIdx.y * TM;
    const int j0 = blockIdx.x * TN;

    // prologue: stages 0,1
#pragma unroll
    for (int s = 0; s < NSTG - 1; s++) { load_chunk(s, s, i0, j0, sb); cp_commit(); }

    const uint32_t aoff = (wm * 64 + (lane & 15)) * ROWB + (lane >> 4) * 16;
    const uint32_t boff = (wn * 64 + (lane & 15)) * ROWB + (lane >> 4) * 16;

    uint32_t afr[2][4][4], bfr[2][4][4];

    float acc[4][8][4];
#pragma unroll
    for (int mi = 0; mi < 4; mi++)
#pragma unroll
        for (int ni = 0; ni < 8; ni++)
#pragma unroll
            for (int q = 0; q < 4; q++) acc[mi][ni][q] = 0.f;

    // ---------------- phase A: fp8 cross (chunks 0..15) ----------------
    for (int c = 0; c < 16; c++) {
        cp_wait<1>();
        __syncthreads();
        int pf = c + NSTG - 1;
        load_chunk(pf, pf % NSTG, i0, j0, sb);
        cp_commit();

        const uint32_t aS = sb + (c % NSTG) * STAGE_SZ;
        const uint32_t bS = aS + A_SZ;
#pragma unroll
        for (int mi = 0; mi < 4; mi++) ldsm4(aS + aoff + mi * (16 * ROWB), afr[0][mi]);
#pragma unroll
        for (int np = 0; np < 4; np++) ldsm4(bS + boff + np * (16 * ROWB), bfr[0][np]);
#pragma unroll
        for (int ks = 0; ks < 4; ks++) {       // 4 x k32 (32 B each)
            const int cur = ks & 1, nxt = cur ^ 1;
            if (ks < 3) {
#pragma unroll
                for (int mi = 0; mi < 4; mi++)
                    ldsm4(aS + aoff + mi * (16 * ROWB) + (ks + 1) * 32, afr[nxt][mi]);
#pragma unroll
                for (int np = 0; np < 4; np++)
                    ldsm4(bS + boff + np * (16 * ROWB) + (ks + 1) * 32, bfr[nxt][np]);
            }
#pragma unroll
            for (int mi = 0; mi < 4; mi++)
#pragma unroll
                for (int ni = 0; ni < 8; ni++)
                    mma_fp8(acc[mi][ni], afr[cur][mi],
                            bfr[cur][ni >> 1][ni & 1], bfr[cur][ni >> 1][(ni & 1) + 2]);
        }
    }

    // un-scale the cross term
#pragma unroll
    for (int mi = 0; mi < 4; mi++)
#pragma unroll
        for (int ni = 0; ni < 8; ni++)
#pragma unroll
            for (int q = 0; q < 4; q++) acc[mi][ni][q] *= LO_UNSCALE;

    // ---------------- phase B: fp16 hihi (chunks 16..31) ----------------
    for (int c = 16; c < NCH; c++) {
        cp_wait<1>();
        __syncthreads();
        int pf = c + NSTG - 1;
        if (pf < NCH) { load_chunk(pf, pf % NSTG, i0, j0, sb); cp_commit(); }

        const uint32_t aS = sb + (c % NSTG) * STAGE_SZ;
        const uint32_t bS = aS + A_SZ;
#pragma unroll
        for (int mi = 0; mi < 4; mi++) ldsm4(aS + aoff + mi * (16 * ROWB), afr[0][mi]);
#pragma unroll
        for (int np = 0; np < 4; np++) ldsm4(bS + boff + np * (16 * ROWB), bfr[0][np]);
#pragma unroll
        for (int ks = 0; ks < 4; ks++) {       // 4 x k16 (32 B each)
            const int cur = ks & 1, nxt = cur ^ 1;
            if (ks < 3) {
#pragma unroll
                for (int mi = 0; mi < 4; mi++)
                    ldsm4(aS + aoff + mi * (16 * ROWB) + (ks + 1) * 32, afr[nxt][mi]);
#pragma unroll
                for (int np = 0; np < 4; np++)
                    ldsm4(bS + boff + np * (16 * ROWB) + (ks + 1) * 32, bfr[nxt][np]);
            }
#pragma unroll
            for (int mi = 0; mi < 4; mi++)
#pragma unroll
                for (int ni = 0; ni < 8; ni++)
                    mma_f32(acc[mi][ni], afr[cur][mi],
                            bfr[cur][ni >> 1][ni & 1], bfr[cur][ni >> 1][(ni & 1) + 2]);
        }
    }

    // ---------------- epilogue ----------------
    float cv0[4], cv1[4];
#pragma unroll
    for (int mi = 0; mi < 4; mi++) {
        int r0 = i0 + wm * 64 + mi * 16 + (lane >> 2);
        cv0[mi] = g_c[r0];
        cv1[mi] = g_c[r0 + 8];
    }
    float cjv[8][2];
#pragma unroll
    for (int ni = 0; ni < 8; ni++) {
        int cb = j0 + wn * 64 + (ni >> 1) * 16 + (ni & 1) * 8 + (lane & 3) * 2;
        cjv[ni][0] = g_cj[cb];
        cjv[ni][1] = g_cj[cb + 1];
    }

#pragma unroll
    for (int mi = 0; mi < 4; mi++) {
        const int r0 = i0 + wm * 64 + mi * 16 + (lane >> 2);
        const int r1 = r0 + 8;
        float rs0 = 0.f, rs1 = 0.f;
#pragma unroll
        for (int ni = 0; ni < 8; ni++) {
            const int cb = j0 + wn * 64 + (ni >> 1) * 16 + (ni & 1) * 8 + (lane & 3) * 2;
            float e0 = __expf(cv0[mi] + cjv[ni][0] - 0.1f * acc[mi][ni][0]);
            float e1 = __expf(cv0[mi] + cjv[ni][1] - 0.1f * acc[mi][ni][1]);
            float e2 = __expf(cv1[mi] + cjv[ni][0] - 0.1f * acc[mi][ni][2]);
            float e3 = __expf(cv1[mi] + cjv[ni][1] - 0.1f * acc[mi][ni][3]);
            if (cb     == r0) e0 = 0.f;
            if (cb + 1 == r0) e1 = 0.f;
            if (cb     == r1) e2 = 0.f;
            if (cb + 1 == r1) e3 = 0.f;
            rs0 += e0 + e1;
            rs1 += e2 + e3;
            if (write_logits) {
                if (cb     != r0) out[(size_t)r0 * NM1 + cb     - (cb     > r0)] = e0;
                if (cb + 1 != r0) out[(size_t)r0 * NM1 + cb + 1 - (cb + 1 > r0)] = e1;
                if (cb     != r1) out[(size_t)r1 * NM1 + cb     - (cb     > r1)] = e2;
                if (cb + 1 != r1) out[(size_t)r1 * NM1 + cb + 1 - (cb + 1 > r1)] = e3;
            }
        }
        rs0 += __shfl_xor_sync(0xFFFFFFFFu, rs0, 1);
        rs0 += __shfl_xor_sync(0xFFFFFFFFu, rs0, 2);
        rs1 += __shfl_xor_sync(0xFFFFFFFFu, rs1, 1);
        rs1 += __shfl_xor_sync(0xFFFFFFFFu, rs1, 2);
        if ((lane & 3) == 0) {
            atomicAdd(&g_rowsum[r0], rs0);
            atomicAdd(&g_rowsum[r1], rs1);
        }
    }
}

// ---------------- loss = mean(log(rowsum)) ----------------
__global__ void loss_kernel(float* __restrict__ loss_out) {
    __shared__ float sh[1024];
    float p = 0.f;
    for (int i = threadIdx.x; i < B2; i += 1024) p += __logf(g_rowsum[i]);
    sh[threadIdx.x] = p;
    __syncthreads();
    for (int st = 512; st > 0; st >>= 1) {
        if (threadIdx.x < st) sh[threadIdx.x] += sh[threadIdx.x + st];
        __syncthreads();
    }
    if (threadIdx.x == 0) *loss_out = sh[0] / (float)B2;
}

// ---------------- launch ----------------
extern "C" void kernel_launch(void* const* d_in, const int* in_sizes, int n_in,
                              void* d_out, int out_size) {
    const float* f     = (const float*)d_in[0];
    const float* s     = (const float*)d_in[1];
    const int*   label = (const int*)d_in[2];

    float* outf = (float*)d_out;
    const long long LOGN = (long long)B2 * NM1;
    float* loss_out  = nullptr;
    float* logit_out = nullptr;
    if ((long long)out_size == LOGN + 1) { loss_out = outf; logit_out = outf + 1; }
    else if ((long long)out_size == LOGN) { logit_out = outf; }
    else { loss_out = outf; }

    cudaFuncSetAttribute(dist_kernel, cudaFuncAttributeMaxDynamicSharedMemorySize, SM_TOTAL);

    prep_kernel<<<B2, 128>>>(f, s);
    gt_kernel<<<B2, 256>>>(f, s, label);

    dim3 grid(B2 / TN, B2 / TM);
    dist_kernel<<<grid, 128, SM_TOTAL>>>(logit_out ? logit_out : outf,
                                         logit_out != nullptr ? 1 : 0);

    if (loss_out) loss_kernel<<<1, 1024>>>(loss_out);
}